// round 7
// baseline (speedup 1.0000x reference)
#include <cuda_runtime.h>
#include <cstddef>

// out[b,i,j]: pairwise-sorted, per-column cyclically shifted v (B=8, L=4096, D=1024 fp32).
//   s_j = (j==0) ? 0 : 2*(j-1)   (always even)
//   out pair (i, i+1), i even:  sort( v[(i-s_j)%L, j], v[(i+1-s_j)%L, j] )
//
// Tile: R=256 output rows x C=32 cols per CTA.
// Smem band is PRE-SHIFTED per column with a 64-row margin on both sides:
//   store row for column j at band row rr is  rr - off_j + PAD  in [2, 383]
//   -> no predication in the load loop.
// Load:    LDG.128 + 4 unpredicated STS.32 (bank = rr+12q+3k -> conflict-free).
// Consume: 5x LDS.64, all at even float offsets (row-b read via the even
//          offset base+STRIDE-1 with lane-shifted extraction), bank-pair
//          (p+2q) mod 16 -> conflict-free per 16-lane phase; + 2x STG.128.

namespace {
constexpr int L      = 4096;
constexpr int D      = 1024;
constexpr int C      = 32;     // columns per tile
constexpr int R      = 256;    // output rows per tile
constexpr int STRIDE = 33;     // smem row stride (floats)
constexpr int PAD    = 64;     // margin rows
constexpr int ROWS   = R + 2 * PAD;   // 384
constexpr int BAND   = R + 64; // global rows loaded per tile
constexpr int NT     = 512;
constexpr size_t SMEM_BYTES = (size_t)ROWS * STRIDE * sizeof(float);  // 50688
}

__global__ __launch_bounds__(NT)
void swd_kernel(const float* __restrict__ v, float* __restrict__ out) {
    extern __shared__ float s[];

    const int i0 = blockIdx.x * R;    // row tile (fastest -> halo L2 reuse)
    const int j0 = blockIdx.y * C;    // column tile
    const int b  = blockIdx.z;

    const int q  = threadIdx.x & 7;   // column quad (4 cols)
    const int tr = threadIdx.x >> 3;  // 0..63

    const int j_hi      = j0 + C - 1;           // >= 31
    const int shift_hi  = 2 * (j_hi - 1);
    const int band_base = i0 - shift_hi;        // may be negative (mask wraps)

    const float* __restrict__ vb = v   + (size_t)b * (L * D);
    float*       __restrict__ ob = out + (size_t)b * (L * D);

    const int cb = 4 * q;

    // Per-column smem float offset: (PAD - off_k)*STRIDE + cb + k, off in [0,62]
    int sofs[4];
    #pragma unroll
    for (int k = 0; k < 4; k++) {
        int j   = j0 + cb + k;
        int sj  = (j == 0) ? 0 : 2 * (j - 1);
        sofs[k] = (PAD - (shift_hi - sj)) * STRIDE + cb + k;
    }

    // ---- Load band: LDG.128 + 4 unpredicated STS.32 per iteration ----
    #pragma unroll
    for (int it = 0; it < BAND / 64; it++) {   // 5 iterations
        int rr = it * 64 + tr;                 // band row 0..319
        int g  = (band_base + rr) & (L - 1);
        float4 val = *reinterpret_cast<const float4*>(vb + (size_t)g * D + (j0 + cb));
        float* srow = s + rr * STRIDE;
        srow[sofs[0]] = val.x;
        srow[sofs[1]] = val.y;
        srow[sofs[2]] = val.z;
        srow[sofs[3]] = val.w;
    }
    __syncthreads();

    // ---- Consume: 5x LDS.64 + min/max + 2x STG.128 ----
    #pragma unroll
    for (int it = 0; it < (R / 2) * 8 / NT; it++) {   // 2 iterations
        int p = it * 64 + tr;                          // pair 0..127
        const float* base = s + (PAD + 2 * p) * STRIDE + cb;   // even offset
        float2 a01 = *reinterpret_cast<const float2*>(base);
        float2 a23 = *reinterpret_cast<const float2*>(base + 2);
        // row b starts at base + STRIDE (odd). Read from even offset
        // base + STRIDE - 1; first/last extracted lanes are discarded junk
        // (in-bounds: pad column / adjacent row slot).
        const float* r1m = base + (STRIDE - 1);
        float2 t0 = *reinterpret_cast<const float2*>(r1m);       // {x: junk, y: b0}
        float2 t1 = *reinterpret_cast<const float2*>(r1m + 2);   // {b1, b2}
        float2 t2 = *reinterpret_cast<const float2*>(r1m + 4);   // {b3, junk}
        float b0 = t0.y, b1 = t1.x, b2 = t1.y, b3 = t2.x;
        float4 lo, hi;
        lo.x = fminf(a01.x, b0); hi.x = fmaxf(a01.x, b0);
        lo.y = fminf(a01.y, b1); hi.y = fmaxf(a01.y, b1);
        lo.z = fminf(a23.x, b2); hi.z = fmaxf(a23.x, b2);
        lo.w = fminf(a23.y, b3); hi.w = fmaxf(a23.y, b3);
        float* dst = ob + (size_t)(i0 + 2 * p) * D + (j0 + cb);
        __stcs(reinterpret_cast<float4*>(dst),     lo);
        __stcs(reinterpret_cast<float4*>(dst + D), hi);
    }
}

extern "C" void kernel_launch(void* const* d_in, const int* in_sizes, int n_in,
                              void* d_out, int out_size) {
    const float* v   = (const float*)d_in[0];
    float*       out = (float*)d_out;
    const int B = in_sizes[0] / (L * D);

    // Unconditional (idempotent host-side call; no static guard).
    cudaFuncSetAttribute(swd_kernel,
                         cudaFuncAttributeMaxDynamicSharedMemorySize,
                         (int)SMEM_BYTES);

    dim3 grid(L / R, D / C, B);   // 16 x 32 x B
    swd_kernel<<<grid, NT, SMEM_BYTES>>>(v, out);
}